// round 4
// baseline (speedup 1.0000x reference)
#include <cuda_runtime.h>
#include <cstdint>

#define NPG 524288           // elements per (b, group)
#define NTOT 33554432        // B*C*H*W

// ---------------- device scratch (static allocation only) ----------------
static __device__ float  d_part[1024 * 2];    // per-block GN partials (sum, sumsq)
static __device__ float  d_weff[8 * 8192];    // [b][k][o], o<64 gate, o>=64 upd
static __device__ float  d_biaseff[8 * 128];
static __device__ float  d_gate[NTOT];        // sigmoid(gate logits)
static __device__ float  d_hw[NTOT];          // column-scan result

// ---------------- f32x2 packed FMA helpers --------------------------------
__device__ __forceinline__ unsigned long long fma2(unsigned long long a,
                                                   unsigned long long b,
                                                   unsigned long long c) {
    unsigned long long d;
    asm("fma.rn.f32x2 %0, %1, %2, %3;" : "=l"(d) : "l"(a), "l"(b), "l"(c));
    return d;
}
__device__ __forceinline__ unsigned long long pack2(float lo, float hi) {
    unsigned long long d;
    asm("mov.b64 %0, {%1, %2};" : "=l"(d) : "f"(lo), "f"(hi));
    return d;
}
__device__ __forceinline__ void unpack2(unsigned long long v, float& lo, float& hi) {
    asm("mov.b64 {%0, %1}, %2;" : "=f"(lo), "=f"(hi) : "l"(v));
}
__device__ __forceinline__ float sigmoidf_fast(float z) {
    return __fdividef(1.0f, 1.0f + __expf(-z));
}

// ---------------- K1: GN partial stats (atomic-free) ---------------------
__global__ __launch_bounds__(256) void k_gn_stats(const float* __restrict__ x) {
    const int grp   = blockIdx.x >> 4;
    const int slice = blockIdx.x & 15;
    const float4* p = (const float4*)x + (size_t)grp * 131072 + slice * 8192;
    float s = 0.f, ss = 0.f;
#pragma unroll 4
    for (int i = threadIdx.x; i < 8192; i += 256) {
        float4 v = p[i];
        s  += (v.x + v.y) + (v.z + v.w);
        ss += (v.x * v.x + v.y * v.y) + (v.z * v.z + v.w * v.w);
    }
    for (int off = 16; off; off >>= 1) {
        s  += __shfl_down_sync(0xffffffffu, s,  off);
        ss += __shfl_down_sync(0xffffffffu, ss, off);
    }
    __shared__ float rs[8], rss[8];
    int w = threadIdx.x >> 5, l = threadIdx.x & 31;
    if (l == 0) { rs[w] = s; rss[w] = ss; }
    __syncthreads();
    if (threadIdx.x == 0) {
        float S = 0.f, SS = 0.f;
#pragma unroll
        for (int i = 0; i < 8; i++) { S += rs[i]; SS += rss[i]; }
        d_part[blockIdx.x * 2 + 0] = S;
        d_part[blockIdx.x * 2 + 1] = SS;
    }
}

// ---------------- K2: finalize stats + fold GN affine into weights -------
// grid 64 = 8 batches x 8 slices. Each block recomputes its batch's 8
// group stats from d_part (cheap, L2-hot) -> no separate finalize kernel.
__global__ __launch_bounds__(256) void k_weff(const float* __restrict__ gw,
                                              const float* __restrict__ gb,
                                              const float* __restrict__ uw,
                                              const float* __restrict__ ub,
                                              const float* __restrict__ gnw,
                                              const float* __restrict__ gnb) {
    const int b = blockIdx.x >> 3;
    const int slice = blockIdx.x & 7;
    __shared__ float smu[8], srstd[8];
    if (threadIdx.x < 8) {
        int g = b * 8 + threadIdx.x;
        double S = 0.0, SS = 0.0;
#pragma unroll
        for (int i = 0; i < 16; i++) {
            S  += (double)d_part[(g * 16 + i) * 2 + 0];
            SS += (double)d_part[(g * 16 + i) * 2 + 1];
        }
        const double n = (double)NPG;
        double mu  = S / n;
        double var = SS / n - mu * mu;
        smu[threadIdx.x]   = (float)mu;
        srstd[threadIdx.x] = (float)(1.0 / sqrt(var + 1e-5));
    }
    __syncthreads();
    const int base = slice * 1024;
#pragma unroll 4
    for (int i = 0; i < 4; i++) {
        int idx = base + i * 256 + threadIdx.x;
        int k = idx >> 7, o = idx & 127;
        float w = (o < 64) ? gw[o * 64 + k] : uw[(o - 64) * 64 + k];
        d_weff[b * 8192 + idx] = w * gnw[k] * srstd[k >> 3];
    }
    if (slice == 0 && threadIdx.x < 128) {
        int o = threadIdx.x;
        float acc = (o < 64) ? gb[o] : ub[o - 64];
#pragma unroll 8
        for (int k = 0; k < 64; k++) {
            float w = (o < 64) ? gw[o * 64 + k] : uw[(o - 64) * 64 + k];
            int g = k >> 3;
            acc += w * (gnb[k] - smu[g] * srstd[g] * gnw[k]);
        }
        d_biaseff[b * 128 + o] = acc;
    }
}

// ---------------- K3: fused 1x1 convs + column scan over W ---------------
// Grid 2048 = 8 b x 256 h. 256 threads: c = t>>2 (channel), wg = t&3
// (8-pixel group within a 32-pixel chunk). Weights live in SMEM as
// [k][c][{gate,upd}] -> one conflict-free LDS.64 per k. Per k per thread:
// 1 LDS.64 + 2 broadcast LDS.128 + 8 FFMA2 (pipe-bound at 2 CTAs/SM).
// Scan: register-resident affine compose + width-4 shfl Hillis-Steele.
__global__ __launch_bounds__(256, 2) void k_colscan(const float* __restrict__ x) {
    __shared__ float wsm[64 * 128];   // [k][c][2]: k*128 + c*2 + {0=g,1=u}
    __shared__ float hv[64 * 36];     // [k][32 px + 4 pad]

    const int t  = threadIdx.x;
    const int b  = blockIdx.x >> 8;
    const int h  = blockIdx.x & 255;
    const int c  = t >> 2;
    const int wg = t & 3;

    // weights: d_weff[b][k][o] -> wsm[k][o&63][o>>6] (coalesced read)
    {
        const float* wp = d_weff + b * 8192;
#pragma unroll
        for (int i = 0; i < 32; i++) {
            int idx = i * 256 + t;
            int k = idx >> 7, o = idx & 127;
            wsm[k * 128 + (o & 63) * 2 + (o >> 6)] = wp[idx];
        }
    }
    const float bg = d_biaseff[b * 128 + c];
    const float bu = d_biaseff[b * 128 + 64 + c];

    // loader: 2 float4 per thread per chunk (channels t>>3 and t>>3 + 32)
    const float* xbase = x + (((size_t)b * 64) * 256 + h) * 256;
    const float* gA = xbase + (size_t)(t >> 3) * 65536 + (t & 7) * 4;
    const float* gB = xbase + (size_t)((t >> 3) + 32) * 65536 + (t & 7) * 4;
    const int sA = (t >> 3) * 36 + (t & 7) * 4;
    const int sB = sA + 32 * 36;

    float4 vin0 = *(const float4*)gA;      // prefetch chunk 0
    float4 vin1 = *(const float4*)gB;

    float s_prev = 0.f;
    const unsigned FULL = 0xffffffffu;

#pragma unroll 1
    for (int ch = 0; ch < 8; ch++) {
        if (ch) __syncthreads();           // prior readers of hv done
        *(float4*)&hv[sA] = vin0;
        *(float4*)&hv[sB] = vin1;
        __syncthreads();                   // chunk (and, on ch=0, wsm) visible
        if (ch < 7) {                      // prefetch next; latency hides in matvec
            vin0 = *(const float4*)(gA + (ch + 1) * 32);
            vin1 = *(const float4*)(gB + (ch + 1) * 32);
        }

        // ---- matvec: 8 pixels x {gate, upd} ----
        unsigned long long ag0, ag1, ag2, ag3, au0, au1, au2, au3;
        ag0 = ag1 = ag2 = ag3 = pack2(bg, bg);
        au0 = au1 = au2 = au3 = pack2(bu, bu);
        const float* hb = hv + wg * 8;
#pragma unroll
        for (int k = 0; k < 64; k++) {
            float2 wv = *(const float2*)&wsm[k * 128 + c * 2];
            unsigned long long w2g = pack2(wv.x, wv.x);
            unsigned long long w2u = pack2(wv.y, wv.y);
            ulonglong2 hA = *(const ulonglong2*)(hb + k * 36);
            ulonglong2 hB = *(const ulonglong2*)(hb + k * 36 + 4);
            ag0 = fma2(w2g, hA.x, ag0);  au0 = fma2(w2u, hA.x, au0);
            ag1 = fma2(w2g, hA.y, ag1);  au1 = fma2(w2u, hA.y, au1);
            ag2 = fma2(w2g, hB.x, ag2);  au2 = fma2(w2u, hB.x, au2);
            ag3 = fma2(w2g, hB.y, ag3);  au3 = fma2(w2u, hB.y, au3);
        }
        float gv[8], uv[8];
        unpack2(ag0, gv[0], gv[1]); unpack2(ag1, gv[2], gv[3]);
        unpack2(ag2, gv[4], gv[5]); unpack2(ag3, gv[6], gv[7]);
        unpack2(au0, uv[0], uv[1]); unpack2(au1, uv[2], uv[3]);
        unpack2(au2, uv[4], uv[5]); unpack2(au3, uv[6], uv[7]);
#pragma unroll
        for (int j = 0; j < 8; j++) gv[j] = sigmoidf_fast(gv[j]);

        // ---- local affine prefix: s_out = A*s_in + B ----
        float A[8], Bv[8];
        float Ac = 1.f, Bc = 0.f;
#pragma unroll
        for (int j = 0; j < 8; j++) {
            Ac = Ac * gv[j];
            Bc = fmaf(gv[j], Bc, fmaf(-gv[j], uv[j], uv[j]));
            A[j] = Ac; Bv[j] = Bc;
        }
        // ---- width-4 inclusive Hillis-Steele on (A,B) across wg lanes ----
        float Ai = Ac, Bi = Bc;
        {
            float Au = __shfl_up_sync(FULL, Ai, 1, 4);
            float Bu = __shfl_up_sync(FULL, Bi, 1, 4);
            if (wg >= 1) { Bi = fmaf(Ai, Bu, Bi); Ai *= Au; }
            Au = __shfl_up_sync(FULL, Ai, 2, 4);
            Bu = __shfl_up_sync(FULL, Bi, 2, 4);
            if (wg >= 2) { Bi = fmaf(Ai, Bu, Bi); Ai *= Au; }
        }
        float Ax = __shfl_up_sync(FULL, Ai, 1, 4);
        float Bx = __shfl_up_sync(FULL, Bi, 1, 4);
        float sin = (wg == 0) ? s_prev : fmaf(Ax, s_prev, Bx);
        float sv[8];
#pragma unroll
        for (int j = 0; j < 8; j++) sv[j] = fmaf(A[j], sin, Bv[j]);
        // carry to next chunk: inclusive of lane wg=3 applied to s_prev
        float A3 = __shfl_sync(FULL, Ai, 3, 4);
        float B3 = __shfl_sync(FULL, Bi, 3, 4);
        s_prev = fmaf(A3, s_prev, B3);

        // ---- writeback: 4 STG.128 ----
        int gi = (((b * 64 + c) * 256 + h) * 256) + ch * 32 + wg * 8;
        *(float4*)(d_gate + gi)     = make_float4(gv[0], gv[1], gv[2], gv[3]);
        *(float4*)(d_gate + gi + 4) = make_float4(gv[4], gv[5], gv[6], gv[7]);
        *(float4*)(d_hw + gi)       = make_float4(sv[0], sv[1], sv[2], sv[3]);
        *(float4*)(d_hw + gi + 4)   = make_float4(sv[4], sv[5], sv[6], sv[7]);
    }
}

// ---------------- K4: row scan over H + residual add ---------------------
// float4 per thread (32768 threads), h unrolled x2 with batched loads.
__global__ __launch_bounds__(128) void k_rowscan(const float* __restrict__ x,
                                                 float* __restrict__ out) {
    const int idx  = blockIdx.x * 128 + threadIdx.x;       // 0..32767
    const int base = (idx >> 6) * 65536 + (idx & 63) * 4;  // (b*64+c)*HW + 4*w4
    const float4* gp = (const float4*)(d_gate + base);
    const float4* up = (const float4*)(d_hw + base);
    const float4* xp = (const float4*)(x + base);
    float4* op = (float4*)(out + base);
    float4 s = make_float4(0.f, 0.f, 0.f, 0.f);
#pragma unroll 4
    for (int h = 0; h < 256; h += 2) {
        const int r0 = h << 6;            // float4 stride per row = 64
        const int r1 = r0 + 64;
        float4 g0 = __ldcs(gp + r0), g1 = __ldcs(gp + r1);
        float4 u0 = __ldcs(up + r0), u1 = __ldcs(up + r1);
        float4 x0 = __ldcs(xp + r0), x1 = __ldcs(xp + r1);
        s.x = fmaf(g0.x, s.x, fmaf(-g0.x, u0.x, u0.x));
        s.y = fmaf(g0.y, s.y, fmaf(-g0.y, u0.y, u0.y));
        s.z = fmaf(g0.z, s.z, fmaf(-g0.z, u0.z, u0.z));
        s.w = fmaf(g0.w, s.w, fmaf(-g0.w, u0.w, u0.w));
        float4 o0 = make_float4(x0.x + s.x, x0.y + s.y, x0.z + s.z, x0.w + s.w);
        s.x = fmaf(g1.x, s.x, fmaf(-g1.x, u1.x, u1.x));
        s.y = fmaf(g1.y, s.y, fmaf(-g1.y, u1.y, u1.y));
        s.z = fmaf(g1.z, s.z, fmaf(-g1.z, u1.z, u1.z));
        s.w = fmaf(g1.w, s.w, fmaf(-g1.w, u1.w, u1.w));
        float4 o1 = make_float4(x1.x + s.x, x1.y + s.y, x1.z + s.z, x1.w + s.w);
        __stcs(op + r0, o0);
        __stcs(op + r1, o1);
    }
}

// ---------------- launch --------------------------------------------------
extern "C" void kernel_launch(void* const* d_in, const int* in_sizes, int n_in,
                              void* d_out, int out_size) {
    const float* x      = (const float*)d_in[0];
    const float* gn_w   = (const float*)d_in[1];
    const float* gn_b   = (const float*)d_in[2];
    const float* gate_w = (const float*)d_in[3];
    const float* gate_b = (const float*)d_in[4];
    const float* upd_w  = (const float*)d_in[5];
    const float* upd_b  = (const float*)d_in[6];
    float* out = (float*)d_out;

    k_gn_stats<<<1024, 256>>>(x);
    k_weff<<<64, 256>>>(gate_w, gate_b, upd_w, upd_b, gn_w, gn_b);
    k_colscan<<<2048, 256>>>(x);
    k_rowscan<<<256, 128>>>(x, out);
}

// round 5
// speedup vs baseline: 1.2686x; 1.2686x over previous
#include <cuda_runtime.h>
#include <cstdint>

#define NPG 524288           // elements per (b, group)
#define NTOT 33554432        // B*C*H*W

// ---------------- device scratch (static allocation only) ----------------
static __device__ float  d_part[1024 * 2];    // per-block GN partials (sum, sumsq)
static __device__ float  d_weff[8 * 8192];    // [b][k][c*2 + {0=gate,1=upd}]
static __device__ float  d_biaseff[8 * 128];
static __device__ float  d_gate[NTOT];        // sigmoid(gate logits)
static __device__ float  d_hw[NTOT];          // column-scan result

// ---------------- f32x2 packed FMA helpers --------------------------------
__device__ __forceinline__ unsigned long long fma2(unsigned long long a,
                                                   unsigned long long b,
                                                   unsigned long long c) {
    unsigned long long d;
    asm("fma.rn.f32x2 %0, %1, %2, %3;" : "=l"(d) : "l"(a), "l"(b), "l"(c));
    return d;
}
__device__ __forceinline__ unsigned long long pack2(float lo, float hi) {
    unsigned long long d;
    asm("mov.b64 %0, {%1, %2};" : "=l"(d) : "f"(lo), "f"(hi));
    return d;
}
__device__ __forceinline__ void unpack2(unsigned long long v, float& lo, float& hi) {
    asm("mov.b64 {%0, %1}, %2;" : "=f"(lo), "=f"(hi) : "l"(v));
}
__device__ __forceinline__ float sigmoidf_fast(float z) {
    return __fdividef(1.0f, 1.0f + __expf(-z));
}

// ---------------- K1: GN partial stats (atomic-free) ---------------------
__global__ __launch_bounds__(256) void k_gn_stats(const float* __restrict__ x) {
    const int grp   = blockIdx.x >> 4;
    const int slice = blockIdx.x & 15;
    const float4* p = (const float4*)x + (size_t)grp * 131072 + slice * 8192;
    float s = 0.f, ss = 0.f;
#pragma unroll 4
    for (int i = threadIdx.x; i < 8192; i += 256) {
        float4 v = p[i];
        s  += (v.x + v.y) + (v.z + v.w);
        ss += (v.x * v.x + v.y * v.y) + (v.z * v.z + v.w * v.w);
    }
    for (int off = 16; off; off >>= 1) {
        s  += __shfl_down_sync(0xffffffffu, s,  off);
        ss += __shfl_down_sync(0xffffffffu, ss, off);
    }
    __shared__ float rs[8], rss[8];
    int w = threadIdx.x >> 5, l = threadIdx.x & 31;
    if (l == 0) { rs[w] = s; rss[w] = ss; }
    __syncthreads();
    if (threadIdx.x == 0) {
        float S = 0.f, SS = 0.f;
#pragma unroll
        for (int i = 0; i < 8; i++) { S += rs[i]; SS += rss[i]; }
        d_part[blockIdx.x * 2 + 0] = S;
        d_part[blockIdx.x * 2 + 1] = SS;
    }
}

// ---------------- K2: finalize stats + fold GN affine into weights -------
// Writes d_weff in the interleaved [k][c][{g,u}] layout colscan consumes.
__global__ __launch_bounds__(256) void k_weff(const float* __restrict__ gw,
                                              const float* __restrict__ gb,
                                              const float* __restrict__ uw,
                                              const float* __restrict__ ub,
                                              const float* __restrict__ gnw,
                                              const float* __restrict__ gnb) {
    const int b = blockIdx.x >> 3;
    const int slice = blockIdx.x & 7;
    __shared__ float smu[8], srstd[8];
    if (threadIdx.x < 8) {
        int g = b * 8 + threadIdx.x;
        double S = 0.0, SS = 0.0;
#pragma unroll
        for (int i = 0; i < 16; i++) {
            S  += (double)d_part[(g * 16 + i) * 2 + 0];
            SS += (double)d_part[(g * 16 + i) * 2 + 1];
        }
        const double n = (double)NPG;
        double mu  = S / n;
        double var = SS / n - mu * mu;
        smu[threadIdx.x]   = (float)mu;
        srstd[threadIdx.x] = (float)(1.0 / sqrt(var + 1e-5));
    }
    __syncthreads();
    const int base = slice * 1024;
#pragma unroll 4
    for (int i = 0; i < 4; i++) {
        int idx = base + i * 256 + threadIdx.x;
        int k = idx >> 7, o = idx & 127;
        float w = (o < 64) ? gw[o * 64 + k] : uw[(o - 64) * 64 + k];
        // interleaved: [k][c*2 + {0=gate,1=upd}]
        d_weff[b * 8192 + k * 128 + (o & 63) * 2 + (o >> 6)] =
            w * gnw[k] * srstd[k >> 3];
    }
    if (slice == 0 && threadIdx.x < 128) {
        int o = threadIdx.x;
        float acc = (o < 64) ? gb[o] : ub[o - 64];
#pragma unroll 8
        for (int k = 0; k < 64; k++) {
            float w = (o < 64) ? gw[o * 64 + k] : uw[(o - 64) * 64 + k];
            int g = k >> 3;
            acc += w * (gnb[k] - smu[g] * srstd[g] * gnw[k]);
        }
        d_biaseff[b * 128 + o] = acc;
    }
}

// ---------------- K3: fused 1x1 convs + column scan over W ---------------
// Grid 2048 = 8 b x 256 h. 128 threads: c = t>>1 (channel), wg = t&1
// (16-pixel group). Chunk = 32 px, 8 chunks per row. Per k per thread:
// 1 LDS.64 (weights) + 4 broadcast LDS.128 (pixels) -> 16 FFMA2.
// 4 CTAs/SM (165KB smem, regs<=128) -> 16 warps/SM hides latencies.
__global__ __launch_bounds__(128, 4) void k_colscan(const float* __restrict__ x) {
    __shared__ float wsm[64 * 128];   // 32KB: [k][c*2 + {g,u}]
    __shared__ float hv[64 * 36];     // 9.2KB: [k][32 px + 4 pad]

    const int t  = threadIdx.x;
    const int b  = blockIdx.x >> 8;
    const int h  = blockIdx.x & 255;
    const int c  = t >> 1;
    const int wg = t & 1;

    // weights: straight float4 copy (layout pre-interleaved by k_weff)
    {
        const float4* wsrc = (const float4*)(d_weff + b * 8192);
        float4* wdst = (float4*)wsm;
#pragma unroll
        for (int i = 0; i < 16; i++) wdst[t + i * 128] = wsrc[t + i * 128];
    }
    const float bg = d_biaseff[b * 128 + c];
    const float bu = d_biaseff[b * 128 + 64 + c];

    // pixel loader: 4 float4 per thread per chunk; slot = t + i*128
    const float* xb = x + (size_t)b * 64 * 65536 + h * 256;
    float4 vin[4];
#pragma unroll
    for (int i = 0; i < 4; i++) {
        int sl = t + i * 128;
        vin[i] = *(const float4*)(xb + (size_t)(sl >> 3) * 65536 + (sl & 7) * 4);
    }

    float s_prev = 0.f;
    const unsigned FULL = 0xffffffffu;

#pragma unroll 1
    for (int chk = 0; chk < 8; chk++) {
        if (chk) __syncthreads();          // prior readers of hv done
#pragma unroll
        for (int i = 0; i < 4; i++) {
            int sl = t + i * 128;
            *(float4*)&hv[(sl >> 3) * 36 + (sl & 7) * 4] = vin[i];
        }
        __syncthreads();                   // chunk (and, on chk=0, wsm) visible
        if (chk < 7) {
#pragma unroll
            for (int i = 0; i < 4; i++) {
                int sl = t + i * 128;
                vin[i] = *(const float4*)(xb + (size_t)(sl >> 3) * 65536
                                          + (chk + 1) * 32 + (sl & 7) * 4);
            }
        }

        // ---- matvec: 16 pixels x {gate, upd} ----
        unsigned long long ag[8], au[8];
        const unsigned long long bg2 = pack2(bg, bg);
        const unsigned long long bu2 = pack2(bu, bu);
#pragma unroll
        for (int j = 0; j < 8; j++) { ag[j] = bg2; au[j] = bu2; }
        const float* hb = hv + wg * 16;
#pragma unroll
        for (int k = 0; k < 64; k++) {
            float2 wv = *(const float2*)&wsm[k * 128 + c * 2];
            unsigned long long w2g = pack2(wv.x, wv.x);
            unsigned long long w2u = pack2(wv.y, wv.y);
#pragma unroll
            for (int j = 0; j < 4; j++) {
                ulonglong2 hp = *(const ulonglong2*)(hb + k * 36 + j * 4);
                ag[2*j]   = fma2(w2g, hp.x, ag[2*j]);
                au[2*j]   = fma2(w2u, hp.x, au[2*j]);
                ag[2*j+1] = fma2(w2g, hp.y, ag[2*j+1]);
                au[2*j+1] = fma2(w2u, hp.y, au[2*j+1]);
            }
        }
        float gv[16], uv[16];
#pragma unroll
        for (int j = 0; j < 8; j++) {
            unpack2(ag[j], gv[2*j], gv[2*j+1]);
            unpack2(au[j], uv[2*j], uv[2*j+1]);
        }
#pragma unroll
        for (int j = 0; j < 16; j++) gv[j] = sigmoidf_fast(gv[j]);

        // ---- local affine prefix: s_out = A*s_in + B ----
        float A[16], Bv[16];
        float Ac = 1.f, Bc = 0.f;
#pragma unroll
        for (int j = 0; j < 16; j++) {
            Ac = Ac * gv[j];
            Bc = fmaf(gv[j], Bc, fmaf(-gv[j], uv[j], uv[j]));
            A[j] = Ac; Bv[j] = Bc;
        }
        // exchange composites between the two 16-px groups (lane^1)
        float Ao = __shfl_xor_sync(FULL, Ac, 1);
        float Bo = __shfl_xor_sync(FULL, Bc, 1);
        // first half composite (wg0): own for wg0, other for wg1
        float Af = (wg == 0) ? Ac : Ao;
        float Bf = (wg == 0) ? Bc : Bo;
        float As = (wg == 0) ? Ao : Ac;
        float Bs = (wg == 0) ? Bo : Bc;
        float sin = (wg == 0) ? s_prev : fmaf(Af, s_prev, Bf);
        float sv[16];
#pragma unroll
        for (int j = 0; j < 16; j++) sv[j] = fmaf(A[j], sin, Bv[j]);
        s_prev = fmaf(As, fmaf(Af, s_prev, Bf), Bs);

        // ---- writeback: 4+4 STG.128 ----
        int gi = (((b * 64 + c) * 256 + h) * 256) + chk * 32 + wg * 16;
#pragma unroll
        for (int j = 0; j < 4; j++) {
            *(float4*)(d_gate + gi + j * 4) =
                make_float4(gv[4*j], gv[4*j+1], gv[4*j+2], gv[4*j+3]);
            *(float4*)(d_hw + gi + j * 4) =
                make_float4(sv[4*j], sv[4*j+1], sv[4*j+2], sv[4*j+3]);
        }
    }
}

// ---------------- K4: row scan over H + residual add ---------------------
// Scalar, 131072 threads (one per (b,c,w)) for max latency tolerance.
__global__ __launch_bounds__(256) void k_rowscan(const float* __restrict__ x,
                                                 float* __restrict__ out) {
    const int idx  = blockIdx.x * 256 + threadIdx.x;     // 0..131071
    const int base = (idx >> 8) * 65536 + (idx & 255);   // (b*64+c)*HW + w
    float s = 0.f;
#pragma unroll 8
    for (int h = 0; h < 256; h++) {
        int p = base + (h << 8);
        float g  = __ldcs(&d_gate[p]);
        float u  = __ldcs(&d_hw[p]);
        float xv = __ldcs(&x[p]);
        s = fmaf(g, s, fmaf(-g, u, u));
        __stcs(&out[p], xv + s);
    }
}

// ---------------- launch --------------------------------------------------
extern "C" void kernel_launch(void* const* d_in, const int* in_sizes, int n_in,
                              void* d_out, int out_size) {
    const float* x      = (const float*)d_in[0];
    const float* gn_w   = (const float*)d_in[1];
    const float* gn_b   = (const float*)d_in[2];
    const float* gate_w = (const float*)d_in[3];
    const float* gate_b = (const float*)d_in[4];
    const float* upd_w  = (const float*)d_in[5];
    const float* upd_b  = (const float*)d_in[6];
    float* out = (float*)d_out;

    k_gn_stats<<<1024, 256>>>(x);
    k_weff<<<64, 256>>>(gate_w, gate_b, upd_w, upd_b, gn_w, gn_b);
    k_colscan<<<2048, 128>>>(x);
    k_rowscan<<<512, 256>>>(x, out);
}

// round 6
// speedup vs baseline: 1.5673x; 1.2354x over previous
#include <cuda_runtime.h>
#include <cstdint>

#define NPG 524288           // elements per (b, group)
#define NTOT 33554432        // B*C*H*W

// ---------------- device scratch (static allocation only) ----------------
static __device__ float  d_part[1024 * 2];    // per-block GN partials (sum, sumsq)
static __device__ float  d_weff[8 * 8192];    // [b][k][c*2 + {0=gate,1=upd}]
static __device__ float  d_biaseff[8 * 128];
static __device__ float  d_gate[NTOT];        // sigmoid(gate logits)
static __device__ float  d_hw[NTOT];          // column-scan result

// ---------------- f32x2 packed FMA helpers --------------------------------
__device__ __forceinline__ unsigned long long fma2(unsigned long long a,
                                                   unsigned long long b,
                                                   unsigned long long c) {
    unsigned long long d;
    asm("fma.rn.f32x2 %0, %1, %2, %3;" : "=l"(d) : "l"(a), "l"(b), "l"(c));
    return d;
}
__device__ __forceinline__ unsigned long long pack2(float lo, float hi) {
    unsigned long long d;
    asm("mov.b64 %0, {%1, %2};" : "=l"(d) : "f"(lo), "f"(hi));
    return d;
}
__device__ __forceinline__ void unpack2(unsigned long long v, float& lo, float& hi) {
    asm("mov.b64 {%0, %1}, %2;" : "=f"(lo), "=f"(hi) : "l"(v));
}
__device__ __forceinline__ float sigmoidf_fast(float z) {
    return __fdividef(1.0f, 1.0f + __expf(-z));
}

// ---------------- K1: GN partial stats (atomic-free) ---------------------
__global__ __launch_bounds__(256) void k_gn_stats(const float* __restrict__ x) {
    const int grp   = blockIdx.x >> 4;
    const int slice = blockIdx.x & 15;
    const float4* p = (const float4*)x + (size_t)grp * 131072 + slice * 8192;
    float s = 0.f, ss = 0.f;
#pragma unroll 4
    for (int i = threadIdx.x; i < 8192; i += 256) {
        float4 v = p[i];
        s  += (v.x + v.y) + (v.z + v.w);
        ss += (v.x * v.x + v.y * v.y) + (v.z * v.z + v.w * v.w);
    }
    for (int off = 16; off; off >>= 1) {
        s  += __shfl_down_sync(0xffffffffu, s,  off);
        ss += __shfl_down_sync(0xffffffffu, ss, off);
    }
    __shared__ float rs[8], rss[8];
    int w = threadIdx.x >> 5, l = threadIdx.x & 31;
    if (l == 0) { rs[w] = s; rss[w] = ss; }
    __syncthreads();
    if (threadIdx.x == 0) {
        float S = 0.f, SS = 0.f;
#pragma unroll
        for (int i = 0; i < 8; i++) { S += rs[i]; SS += rss[i]; }
        d_part[blockIdx.x * 2 + 0] = S;
        d_part[blockIdx.x * 2 + 1] = SS;
    }
}

// ---------------- K2: finalize stats + fold GN affine into weights -------
__global__ __launch_bounds__(256) void k_weff(const float* __restrict__ gw,
                                              const float* __restrict__ gb,
                                              const float* __restrict__ uw,
                                              const float* __restrict__ ub,
                                              const float* __restrict__ gnw,
                                              const float* __restrict__ gnb) {
    const int b = blockIdx.x >> 3;
    const int slice = blockIdx.x & 7;
    __shared__ float smu[8], srstd[8];
    if (threadIdx.x < 8) {
        int g = b * 8 + threadIdx.x;
        double S = 0.0, SS = 0.0;
#pragma unroll
        for (int i = 0; i < 16; i++) {
            S  += (double)d_part[(g * 16 + i) * 2 + 0];
            SS += (double)d_part[(g * 16 + i) * 2 + 1];
        }
        const double n = (double)NPG;
        double mu  = S / n;
        double var = SS / n - mu * mu;
        smu[threadIdx.x]   = (float)mu;
        srstd[threadIdx.x] = (float)(1.0 / sqrt(var + 1e-5));
    }
    __syncthreads();
    const int base = slice * 1024;
#pragma unroll 4
    for (int i = 0; i < 4; i++) {
        int idx = base + i * 256 + threadIdx.x;
        int k = idx >> 7, o = idx & 127;
        float w = (o < 64) ? gw[o * 64 + k] : uw[(o - 64) * 64 + k];
        // interleaved: [k][c*2 + {0=gate,1=upd}]
        d_weff[b * 8192 + k * 128 + (o & 63) * 2 + (o >> 6)] =
            w * gnw[k] * srstd[k >> 3];
    }
    if (slice == 0 && threadIdx.x < 128) {
        int o = threadIdx.x;
        float acc = (o < 64) ? gb[o] : ub[o - 64];
#pragma unroll 8
        for (int k = 0; k < 64; k++) {
            float w = (o < 64) ? gw[o * 64 + k] : uw[(o - 64) * 64 + k];
            int g = k >> 3;
            acc += w * (gnb[k] - smu[g] * srstd[g] * gnw[k]);
        }
        d_biaseff[b * 128 + o] = acc;
    }
}

// ---------------- K3: fused 1x1 convs + column scan over W ---------------
// Grid 2048 = 8 b x 256 h. 128 threads: c = t>>1, wg = t&1 (16-px group).
// Per k per thread: 1 LDS.64 + 4 broadcast LDS.128 -> 16 FFMA2. 4 CTAs/SM.
__global__ __launch_bounds__(128, 4) void k_colscan(const float* __restrict__ x) {
    __shared__ float wsm[64 * 128];   // 32KB: [k][c*2 + {g,u}]
    __shared__ float hv[64 * 36];     // 9.2KB: [k][32 px + 4 pad]

    const int t  = threadIdx.x;
    const int b  = blockIdx.x >> 8;
    const int h  = blockIdx.x & 255;
    const int c  = t >> 1;
    const int wg = t & 1;

    {
        const float4* wsrc = (const float4*)(d_weff + b * 8192);
        float4* wdst = (float4*)wsm;
#pragma unroll
        for (int i = 0; i < 16; i++) wdst[t + i * 128] = wsrc[t + i * 128];
    }
    const float bg = d_biaseff[b * 128 + c];
    const float bu = d_biaseff[b * 128 + 64 + c];

    const float* xb = x + (size_t)b * 64 * 65536 + h * 256;
    float4 vin[4];
#pragma unroll
    for (int i = 0; i < 4; i++) {
        int sl = t + i * 128;
        vin[i] = *(const float4*)(xb + (size_t)(sl >> 3) * 65536 + (sl & 7) * 4);
    }

    float s_prev = 0.f;
    const unsigned FULL = 0xffffffffu;

#pragma unroll 1
    for (int chk = 0; chk < 8; chk++) {
        if (chk) __syncthreads();
#pragma unroll
        for (int i = 0; i < 4; i++) {
            int sl = t + i * 128;
            *(float4*)&hv[(sl >> 3) * 36 + (sl & 7) * 4] = vin[i];
        }
        __syncthreads();
        if (chk < 7) {
#pragma unroll
            for (int i = 0; i < 4; i++) {
                int sl = t + i * 128;
                vin[i] = *(const float4*)(xb + (size_t)(sl >> 3) * 65536
                                          + (chk + 1) * 32 + (sl & 7) * 4);
            }
        }

        // ---- matvec: 16 pixels x {gate, upd} ----
        unsigned long long ag[8], au[8];
        const unsigned long long bg2 = pack2(bg, bg);
        const unsigned long long bu2 = pack2(bu, bu);
#pragma unroll
        for (int j = 0; j < 8; j++) { ag[j] = bg2; au[j] = bu2; }
        const float* hb = hv + wg * 16;
#pragma unroll
        for (int k = 0; k < 64; k++) {
            float2 wv = *(const float2*)&wsm[k * 128 + c * 2];
            unsigned long long w2g = pack2(wv.x, wv.x);
            unsigned long long w2u = pack2(wv.y, wv.y);
#pragma unroll
            for (int j = 0; j < 4; j++) {
                ulonglong2 hp = *(const ulonglong2*)(hb + k * 36 + j * 4);
                ag[2*j]   = fma2(w2g, hp.x, ag[2*j]);
                au[2*j]   = fma2(w2u, hp.x, au[2*j]);
                ag[2*j+1] = fma2(w2g, hp.y, ag[2*j+1]);
                au[2*j+1] = fma2(w2u, hp.y, au[2*j+1]);
            }
        }
        float gv[16], uv[16];
#pragma unroll
        for (int j = 0; j < 8; j++) {
            unpack2(ag[j], gv[2*j], gv[2*j+1]);
            unpack2(au[j], uv[2*j], uv[2*j+1]);
        }
#pragma unroll
        for (int j = 0; j < 16; j++) gv[j] = sigmoidf_fast(gv[j]);

        // ---- local affine prefix + cross-lane compose ----
        float A[16], Bv[16];
        float Ac = 1.f, Bc = 0.f;
#pragma unroll
        for (int j = 0; j < 16; j++) {
            Ac = Ac * gv[j];
            Bc = fmaf(gv[j], Bc, fmaf(-gv[j], uv[j], uv[j]));
            A[j] = Ac; Bv[j] = Bc;
        }
        float Ao = __shfl_xor_sync(FULL, Ac, 1);
        float Bo = __shfl_xor_sync(FULL, Bc, 1);
        float Af = (wg == 0) ? Ac : Ao;
        float Bf = (wg == 0) ? Bc : Bo;
        float As = (wg == 0) ? Ao : Ac;
        float Bs = (wg == 0) ? Bo : Bc;
        float sin = (wg == 0) ? s_prev : fmaf(Af, s_prev, Bf);
        float sv[16];
#pragma unroll
        for (int j = 0; j < 16; j++) sv[j] = fmaf(A[j], sin, Bv[j]);
        s_prev = fmaf(As, fmaf(Af, s_prev, Bf), Bs);

        // ---- writeback: 4+4 STG.128 (default policy -> keep L2-hot) ----
        int gi = (((b * 64 + c) * 256 + h) * 256) + chk * 32 + wg * 16;
#pragma unroll
        for (int j = 0; j < 4; j++) {
            *(float4*)(d_gate + gi + j * 4) =
                make_float4(gv[4*j], gv[4*j+1], gv[4*j+2], gv[4*j+3]);
            *(float4*)(d_hw + gi + j * 4) =
                make_float4(sv[4*j], sv[4*j+1], sv[4*j+2], sv[4*j+3]);
        }
    }
}

// ---------------- K4: row scan over H + residual add ---------------------
// float2 per thread (65536 threads). Loads for 4 h-steps are explicitly
// batched into register arrays (12 independent LDG.64 in flight) before
// the serial scan math -> MLP_eff ~12 instead of ~3.
__global__ __launch_bounds__(256) void k_rowscan(const float* __restrict__ x,
                                                 float* __restrict__ out) {
    const int idx  = blockIdx.x * 256 + threadIdx.x;       // 0..65535
    const int base = (idx >> 7) * 65536 + (idx & 127) * 2; // (b*64+c)*HW + 2*w2
    const float2* gp = (const float2*)(d_gate + base);
    const float2* up = (const float2*)(d_hw + base);
    const float2* xp = (const float2*)(x + base);
    float2* op = (float2*)(out + base);
    float sa = 0.f, sb = 0.f;
#pragma unroll 1
    for (int h = 0; h < 256; h += 4) {
        const int r = h << 7;              // float2 row stride = 128
        float2 g[4], u[4], xv[4];
#pragma unroll
        for (int j = 0; j < 4; j++) g[j] = gp[r + j * 128];
#pragma unroll
        for (int j = 0; j < 4; j++) u[j] = up[r + j * 128];
#pragma unroll
        for (int j = 0; j < 4; j++) xv[j] = __ldcs(xp + r + j * 128);
#pragma unroll
        for (int j = 0; j < 4; j++) {
            sa = fmaf(g[j].x, sa, fmaf(-g[j].x, u[j].x, u[j].x));
            sb = fmaf(g[j].y, sb, fmaf(-g[j].y, u[j].y, u[j].y));
            __stcs(op + r + j * 128, make_float2(xv[j].x + sa, xv[j].y + sb));
        }
    }
}

// ---------------- launch --------------------------------------------------
extern "C" void kernel_launch(void* const* d_in, const int* in_sizes, int n_in,
                              void* d_out, int out_size) {
    const float* x      = (const float*)d_in[0];
    const float* gn_w   = (const float*)d_in[1];
    const float* gn_b   = (const float*)d_in[2];
    const float* gate_w = (const float*)d_in[3];
    const float* gate_b = (const float*)d_in[4];
    const float* upd_w  = (const float*)d_in[5];
    const float* upd_b  = (const float*)d_in[6];
    float* out = (float*)d_out;

    k_gn_stats<<<1024, 256>>>(x);
    k_weff<<<64, 256>>>(gate_w, gate_b, upd_w, upd_b, gn_w, gn_b);
    k_colscan<<<2048, 128>>>(x);
    k_rowscan<<<256, 256>>>(x, out);
}

// round 7
// speedup vs baseline: 1.5750x; 1.0049x over previous
#include <cuda_runtime.h>
#include <cstdint>

#define NPG 524288           // elements per (b, group)
#define NTOT 33554432        // B*C*H*W

// ---------------- device scratch (static allocation only) ----------------
static __device__ float  d_part[1024 * 2];    // per-block GN partials (sum, sumsq)
static __device__ float  d_weff[8 * 8192];    // [b][k][c*2 + {0=gate,1=upd}]
static __device__ float  d_biaseff[8 * 128];
static __device__ float  d_gate[NTOT];        // sigmoid(gate logits)
static __device__ float  d_hw[NTOT];          // column-scan result

// ---------------- f32x2 packed FMA helpers --------------------------------
__device__ __forceinline__ unsigned long long fma2(unsigned long long a,
                                                   unsigned long long b,
                                                   unsigned long long c) {
    unsigned long long d;
    asm("fma.rn.f32x2 %0, %1, %2, %3;" : "=l"(d) : "l"(a), "l"(b), "l"(c));
    return d;
}
__device__ __forceinline__ unsigned long long pack2(float lo, float hi) {
    unsigned long long d;
    asm("mov.b64 %0, {%1, %2};" : "=l"(d) : "f"(lo), "f"(hi));
    return d;
}
__device__ __forceinline__ void unpack2(unsigned long long v, float& lo, float& hi) {
    asm("mov.b64 {%0, %1}, %2;" : "=f"(lo), "=f"(hi) : "l"(v));
}
// sigmoid(z) = 0.5*tanh(0.5z) + 0.5 via MUFU.TANH (1 MUFU + 2 FMA)
__device__ __forceinline__ float sigmoid_tanh(float z) {
    float t;
    asm("tanh.approx.f32 %0, %1;" : "=f"(t) : "f"(z * 0.5f));
    return fmaf(0.5f, t, 0.5f);
}

// ---------------- K1: GN partial stats (atomic-free) ---------------------
__global__ __launch_bounds__(256) void k_gn_stats(const float* __restrict__ x) {
    const int grp   = blockIdx.x >> 4;
    const int slice = blockIdx.x & 15;
    const float4* p = (const float4*)x + (size_t)grp * 131072 + slice * 8192;
    float s = 0.f, ss = 0.f;
#pragma unroll 4
    for (int i = threadIdx.x; i < 8192; i += 256) {
        float4 v = p[i];
        s  += (v.x + v.y) + (v.z + v.w);
        ss += (v.x * v.x + v.y * v.y) + (v.z * v.z + v.w * v.w);
    }
    for (int off = 16; off; off >>= 1) {
        s  += __shfl_down_sync(0xffffffffu, s,  off);
        ss += __shfl_down_sync(0xffffffffu, ss, off);
    }
    __shared__ float rs[8], rss[8];
    int w = threadIdx.x >> 5, l = threadIdx.x & 31;
    if (l == 0) { rs[w] = s; rss[w] = ss; }
    __syncthreads();
    if (threadIdx.x == 0) {
        float S = 0.f, SS = 0.f;
#pragma unroll
        for (int i = 0; i < 8; i++) { S += rs[i]; SS += rss[i]; }
        d_part[blockIdx.x * 2 + 0] = S;
        d_part[blockIdx.x * 2 + 1] = SS;
    }
}

// ---------------- K2: finalize stats + fold GN affine into weights -------
__global__ __launch_bounds__(256) void k_weff(const float* __restrict__ gw,
                                              const float* __restrict__ gb,
                                              const float* __restrict__ uw,
                                              const float* __restrict__ ub,
                                              const float* __restrict__ gnw,
                                              const float* __restrict__ gnb) {
    const int b = blockIdx.x >> 3;
    const int slice = blockIdx.x & 7;
    __shared__ float smu[8], srstd[8];
    if (threadIdx.x < 8) {
        int g = b * 8 + threadIdx.x;
        double S = 0.0, SS = 0.0;
#pragma unroll
        for (int i = 0; i < 16; i++) {
            S  += (double)d_part[(g * 16 + i) * 2 + 0];
            SS += (double)d_part[(g * 16 + i) * 2 + 1];
        }
        const double n = (double)NPG;
        double mu  = S / n;
        double var = SS / n - mu * mu;
        smu[threadIdx.x]   = (float)mu;
        srstd[threadIdx.x] = (float)(1.0 / sqrt(var + 1e-5));
    }
    __syncthreads();
    const int base = slice * 1024;
#pragma unroll 4
    for (int i = 0; i < 4; i++) {
        int idx = base + i * 256 + threadIdx.x;
        int k = idx >> 7, o = idx & 127;
        float w = (o < 64) ? gw[o * 64 + k] : uw[(o - 64) * 64 + k];
        // interleaved: [k][c*2 + {0=gate,1=upd}]
        d_weff[b * 8192 + k * 128 + (o & 63) * 2 + (o >> 6)] =
            w * gnw[k] * srstd[k >> 3];
    }
    if (slice == 0 && threadIdx.x < 128) {
        int o = threadIdx.x;
        float acc = (o < 64) ? gb[o] : ub[o - 64];
#pragma unroll 8
        for (int k = 0; k < 64; k++) {
            float w = (o < 64) ? gw[o * 64 + k] : uw[(o - 64) * 64 + k];
            int g = k >> 3;
            acc += w * (gnb[k] - smu[g] * srstd[g] * gnw[k]);
        }
        d_biaseff[b * 128 + o] = acc;
    }
}

// ---------------- K3: fused 1x1 convs + column scan over W ---------------
// Grid 2048 = 8 b x 256 h. 128 threads: c = t>>1, wg = t&1 (16-px group).
// Per k per thread: 1 LDS.64 + 4 broadcast LDS.128 -> 16 FFMA2. 4 CTAs/SM.
// Scan uses composite (A,B) exchange + sequential re-apply: no prefix
// arrays -> peak regs ~90, no spills.
__global__ __launch_bounds__(128, 4) void k_colscan(const float* __restrict__ x) {
    __shared__ float wsm[64 * 128];   // 32KB: [k][c*2 + {g,u}]
    __shared__ float hv[64 * 36];     // 9.2KB: [k][32 px + 4 pad]

    const int t  = threadIdx.x;
    const int b  = blockIdx.x >> 8;
    const int h  = blockIdx.x & 255;
    const int c  = t >> 1;
    const int wg = t & 1;

    {
        const float4* wsrc = (const float4*)(d_weff + b * 8192);
        float4* wdst = (float4*)wsm;
#pragma unroll
        for (int i = 0; i < 16; i++) wdst[t + i * 128] = wsrc[t + i * 128];
    }
    const float bg = d_biaseff[b * 128 + c];
    const float bu = d_biaseff[b * 128 + 64 + c];

    const float* xb = x + (size_t)b * 64 * 65536 + h * 256;
    float4 vin[4];
#pragma unroll
    for (int i = 0; i < 4; i++) {
        int sl = t + i * 128;
        vin[i] = *(const float4*)(xb + (size_t)(sl >> 3) * 65536 + (sl & 7) * 4);
    }

    float s_prev = 0.f;
    const unsigned FULL = 0xffffffffu;

#pragma unroll 1
    for (int chk = 0; chk < 8; chk++) {
        if (chk) __syncthreads();
#pragma unroll
        for (int i = 0; i < 4; i++) {
            int sl = t + i * 128;
            *(float4*)&hv[(sl >> 3) * 36 + (sl & 7) * 4] = vin[i];
        }
        __syncthreads();
        if (chk < 7) {
#pragma unroll
            for (int i = 0; i < 4; i++) {
                int sl = t + i * 128;
                vin[i] = *(const float4*)(xb + (size_t)(sl >> 3) * 65536
                                          + (chk + 1) * 32 + (sl & 7) * 4);
            }
        }

        // ---- matvec: 16 pixels x {gate, upd} ----
        unsigned long long ag[8], au[8];
        const unsigned long long bg2 = pack2(bg, bg);
        const unsigned long long bu2 = pack2(bu, bu);
#pragma unroll
        for (int j = 0; j < 8; j++) { ag[j] = bg2; au[j] = bu2; }
        const float* hb = hv + wg * 16;
#pragma unroll
        for (int k = 0; k < 64; k++) {
            float2 wv = *(const float2*)&wsm[k * 128 + c * 2];
            unsigned long long w2g = pack2(wv.x, wv.x);
            unsigned long long w2u = pack2(wv.y, wv.y);
#pragma unroll
            for (int j = 0; j < 4; j++) {
                ulonglong2 hp = *(const ulonglong2*)(hb + k * 36 + j * 4);
                ag[2*j]   = fma2(w2g, hp.x, ag[2*j]);
                au[2*j]   = fma2(w2u, hp.x, au[2*j]);
                ag[2*j+1] = fma2(w2g, hp.y, ag[2*j+1]);
                au[2*j+1] = fma2(w2u, hp.y, au[2*j+1]);
            }
        }
        float gv[16], uv[16];
#pragma unroll
        for (int j = 0; j < 8; j++) {
            unpack2(ag[j], gv[2*j], gv[2*j+1]);
            unpack2(au[j], uv[2*j], uv[2*j+1]);
        }
        // gv -> sigmoid(gate); uv -> (1-g)*u  (folded once, reused twice)
#pragma unroll
        for (int j = 0; j < 16; j++) {
            gv[j] = sigmoid_tanh(gv[j]);
            uv[j] = fmaf(-gv[j], uv[j], uv[j]);
        }

        // ---- composite over own 16 px: (Ac, Bc) ----
        float Ac = 1.f, Bc = 0.f;
#pragma unroll
        for (int j = 0; j < 16; j++) {
            Ac = Ac * gv[j];
            Bc = fmaf(gv[j], Bc, uv[j]);
        }
        // exchange with the neighbour 16-px group (lane^1)
        float Ao = __shfl_xor_sync(FULL, Ac, 1);
        float Bo = __shfl_xor_sync(FULL, Bc, 1);
        float Af = (wg == 0) ? Ac : Ao;   // first-half composite
        float Bf = (wg == 0) ? Bc : Bo;
        float As = (wg == 0) ? Ao : Ac;   // second-half composite
        float Bs = (wg == 0) ? Bc : Bc;   // placeholder; fixed below
        Bs = (wg == 0) ? Bo : Bc;
        float sin = (wg == 0) ? s_prev : fmaf(Af, s_prev, Bf);
        s_prev = fmaf(As, fmaf(Af, s_prev, Bf), Bs);

        // ---- sequential re-apply + writeback (4+4 STG.128) ----
        int gi = (((b * 64 + c) * 256 + h) * 256) + chk * 32 + wg * 16;
        float s = sin;
#pragma unroll
        for (int q = 0; q < 4; q++) {
            float4 sv4;
            s = fmaf(gv[4*q+0], s, uv[4*q+0]); sv4.x = s;
            s = fmaf(gv[4*q+1], s, uv[4*q+1]); sv4.y = s;
            s = fmaf(gv[4*q+2], s, uv[4*q+2]); sv4.z = s;
            s = fmaf(gv[4*q+3], s, uv[4*q+3]); sv4.w = s;
            *(float4*)(d_gate + gi + q * 4) =
                make_float4(gv[4*q], gv[4*q+1], gv[4*q+2], gv[4*q+3]);
            *(float4*)(d_hw + gi + q * 4) = sv4;
        }
    }
}

// ---------------- K4: row scan over H + residual add ---------------------
// Scalar, 131072 threads (1024 x 128). Loads for 8 h-steps explicitly
// batched (24 independent LDG.32 in flight) before the serial scan math.
__global__ __launch_bounds__(128) void k_rowscan(const float* __restrict__ x,
                                                 float* __restrict__ out) {
    const int idx  = blockIdx.x * 128 + threadIdx.x;     // 0..131071
    const int base = (idx >> 8) * 65536 + (idx & 255);   // (b*64+c)*HW + w
    float s = 0.f;
#pragma unroll 1
    for (int h = 0; h < 256; h += 8) {
        const int r = base + (h << 8);
        float g[8], u[8], xv[8];
#pragma unroll
        for (int j = 0; j < 8; j++) g[j] = d_gate[r + (j << 8)];
#pragma unroll
        for (int j = 0; j < 8; j++) u[j] = d_hw[r + (j << 8)];
#pragma unroll
        for (int j = 0; j < 8; j++) xv[j] = __ldcs(&x[r + (j << 8)]);
#pragma unroll
        for (int j = 0; j < 8; j++) {
            s = fmaf(g[j], s, fmaf(-g[j], u[j], u[j]));
            __stcs(&out[r + (j << 8)], xv[j] + s);
        }
    }
}

// ---------------- launch --------------------------------------------------
extern "C" void kernel_launch(void* const* d_in, const int* in_sizes, int n_in,
                              void* d_out, int out_size) {
    const float* x      = (const float*)d_in[0];
    const float* gn_w   = (const float*)d_in[1];
    const float* gn_b   = (const float*)d_in[2];
    const float* gate_w = (const float*)d_in[3];
    const float* gate_b = (const float*)d_in[4];
    const float* upd_w  = (const float*)d_in[5];
    const float* upd_b  = (const float*)d_in[6];
    float* out = (float*)d_out;

    k_gn_stats<<<1024, 256>>>(x);
    k_weff<<<64, 256>>>(gate_w, gate_b, upd_w, upd_b, gn_w, gn_b);
    k_colscan<<<2048, 128>>>(x);
    k_rowscan<<<1024, 128>>>(x, out);
}